// round 8
// baseline (speedup 1.0000x reference)
#include <cuda_runtime.h>
#include <cuda_bf16.h>
#include <math.h>
#include <stdint.h>

// Problem constants
#define B_   2
#define T_   2048
#define DM_  2048
#define HQ_  32
#define HKV_ 8
#define HD_  64
#define G_   4
#define MROWS_ (B_*T_)   // 4096
#define NQKV_ 3072       // 2048 Q + 512 K + 512 V

// ---------------------------------------------------------------------------
// Scratch (device globals)
// ---------------------------------------------------------------------------
__device__ float g_QKVp[(size_t)MROWS_ * NQKV_];       // x @ [WQ;WK;WV]^T fp32

__device__ __nv_bfloat16 g_xhi[(size_t)MROWS_ * DM_];
__device__ __nv_bfloat16 g_xlo[(size_t)MROWS_ * DM_];
__device__ __nv_bfloat16 g_wqkvhi[(size_t)NQKV_ * DM_];
__device__ __nv_bfloat16 g_wqkvlo[(size_t)NQKV_ * DM_];
__device__ __nv_bfloat16 g_wohi[(size_t)DM_ * DM_];
__device__ __nv_bfloat16 g_wolo[(size_t)DM_ * DM_];
__device__ __nv_bfloat16 g_ohi[(size_t)MROWS_ * DM_];
__device__ __nv_bfloat16 g_olo[(size_t)MROWS_ * DM_];

// bf16 hi/lo attention operands, (b,h,t,d) layout
__device__ __nv_bfloat16 g_Qhi[(size_t)B_ * HQ_ * T_ * HD_];
__device__ __nv_bfloat16 g_Qlo[(size_t)B_ * HQ_ * T_ * HD_];
__device__ __nv_bfloat16 g_Khi[(size_t)B_ * HKV_ * T_ * HD_];
__device__ __nv_bfloat16 g_Klo[(size_t)B_ * HKV_ * T_ * HD_];
__device__ __nv_bfloat16 g_Vhi[(size_t)B_ * HKV_ * T_ * HD_];
__device__ __nv_bfloat16 g_Vlo[(size_t)B_ * HKV_ * T_ * HD_];

// ---------------------------------------------------------------------------
// Helpers
// ---------------------------------------------------------------------------
__device__ __forceinline__ uint32_t smem_u32(const void* p) {
    uint32_t a;
    asm("{ .reg .u64 t; cvta.to.shared.u64 t, %1; cvt.u32.u64 %0, t; }" : "=r"(a) : "l"(p));
    return a;
}
__device__ __forceinline__ uint32_t swz128(uint32_t off) { return off ^ ((off >> 3) & 0x70); }
__device__ __forceinline__ uint32_t swz64 (uint32_t off) { return off ^ ((off >> 3) & 0x30); }

__device__ __forceinline__ uint32_t pack_bf16(float lo, float hi) {
    __nv_bfloat162 t = __floats2bfloat162_rn(lo, hi);
    return *(uint32_t*)&t;
}

#define CP16(dst, src) \
    asm volatile("cp.async.cg.shared.global [%0], [%1], 16;" :: "r"(dst), "l"(src))
#define CP_COMMIT() asm volatile("cp.async.commit_group;" ::: "memory")
#define CP_WAIT1()  asm volatile("cp.async.wait_group 1;" ::: "memory")

#define LDM4(R, addr) \
    asm volatile("ldmatrix.sync.aligned.m8n8.x4.shared.b16 {%0,%1,%2,%3}, [%4];" \
        : "=r"((R)[0]), "=r"((R)[1]), "=r"((R)[2]), "=r"((R)[3]) : "r"(addr))
#define LDM4T(R, addr) \
    asm volatile("ldmatrix.sync.aligned.m8n8.x4.trans.shared.b16 {%0,%1,%2,%3}, [%4];" \
        : "=r"((R)[0]), "=r"((R)[1]), "=r"((R)[2]), "=r"((R)[3]) : "r"(addr))

#define MMA_BF16(C, A, b0, b1) \
    asm volatile("mma.sync.aligned.m16n8k16.row.col.f32.bf16.bf16.f32 " \
        "{%0,%1,%2,%3}, {%4,%5,%6,%7}, {%8,%9}, {%0,%1,%2,%3};" \
        : "+f"((C)[0]), "+f"((C)[1]), "+f"((C)[2]), "+f"((C)[3]) \
        : "r"((A)[0]), "r"((A)[1]), "r"((A)[2]), "r"((A)[3]), "r"(b0), "r"(b1))

// ---------------------------------------------------------------------------
// fp32 -> bf16 hi/lo split (single input)
// ---------------------------------------------------------------------------
__global__ __launch_bounds__(256) void split_kernel(
    const float* __restrict__ in, __nv_bfloat16* __restrict__ hi,
    __nv_bfloat16* __restrict__ lo, int n)
{
    int i = (blockIdx.x * 256 + threadIdx.x) * 4;
    if (i >= n) return;
    float4 v = *(const float4*)(in + i);
    __nv_bfloat16 h0 = __float2bfloat16(v.x);
    __nv_bfloat16 h1 = __float2bfloat16(v.y);
    __nv_bfloat16 h2 = __float2bfloat16(v.z);
    __nv_bfloat16 h3 = __float2bfloat16(v.w);
    __nv_bfloat16 l0 = __float2bfloat16(v.x - __bfloat162float(h0));
    __nv_bfloat16 l1 = __float2bfloat16(v.y - __bfloat162float(h1));
    __nv_bfloat16 l2 = __float2bfloat16(v.z - __bfloat162float(h2));
    __nv_bfloat16 l3 = __float2bfloat16(v.w - __bfloat162float(h3));
    __nv_bfloat162* hp = (__nv_bfloat162*)(hi + i);
    __nv_bfloat162* lp = (__nv_bfloat162*)(lo + i);
    hp[0] = __nv_bfloat162{h0, h1}; hp[1] = __nv_bfloat162{h2, h3};
    lp[0] = __nv_bfloat162{l0, l1}; lp[1] = __nv_bfloat162{l2, l3};
}

// ---------------------------------------------------------------------------
// Merged WQ/WK/WV split into packed [3072,2048] hi/lo buffers (one launch)
// ---------------------------------------------------------------------------
__global__ __launch_bounds__(256) void split_wqkv_kernel(
    const float* __restrict__ WQ, const float* __restrict__ WK,
    const float* __restrict__ WV,
    __nv_bfloat16* __restrict__ hi, __nv_bfloat16* __restrict__ lo)
{
    const int NQ = 2048 * DM_;       // 4194304
    const int NK = 512 * DM_;        // 1048576
    int i = (blockIdx.x * 256 + threadIdx.x) * 4;
    if (i >= NQKV_ * DM_) return;
    const float* src;
    int off;
    if (i < NQ)            { src = WQ; off = i; }
    else if (i < NQ + NK)  { src = WK; off = i - NQ; }
    else                   { src = WV; off = i - NQ - NK; }
    float4 v = *(const float4*)(src + off);
    __nv_bfloat16 h0 = __float2bfloat16(v.x);
    __nv_bfloat16 h1 = __float2bfloat16(v.y);
    __nv_bfloat16 h2 = __float2bfloat16(v.z);
    __nv_bfloat16 h3 = __float2bfloat16(v.w);
    __nv_bfloat16 l0 = __float2bfloat16(v.x - __bfloat162float(h0));
    __nv_bfloat16 l1 = __float2bfloat16(v.y - __bfloat162float(h1));
    __nv_bfloat16 l2 = __float2bfloat16(v.z - __bfloat162float(h2));
    __nv_bfloat16 l3 = __float2bfloat16(v.w - __bfloat162float(h3));
    __nv_bfloat162* hp = (__nv_bfloat162*)(hi + i);
    __nv_bfloat162* lp = (__nv_bfloat162*)(lo + i);
    hp[0] = __nv_bfloat162{h0, h1}; hp[1] = __nv_bfloat162{h2, h3};
    lp[0] = __nv_bfloat162{l0, l1}; lp[1] = __nv_bfloat162{l2, l3};
}

// ---------------------------------------------------------------------------
// mma.sync split-bf16 GEMM: C[M,N] = A[M,K] @ B[N,K]^T (fp32-quality)
// CTA 128x128, 8 warps (2x4), warp tile 64x32, K-slab 32, cp.async 2-stage.
// ---------------------------------------------------------------------------
__global__ __launch_bounds__(256) void gemm_mma_kernel(
    const __nv_bfloat16* __restrict__ Ahi, const __nv_bfloat16* __restrict__ Alo,
    const __nv_bfloat16* __restrict__ Bhi, const __nv_bfloat16* __restrict__ Blo,
    float* __restrict__ C, int M, int N, int K)
{
    extern __shared__ char dsm[];
    const uint32_t sbase = smem_u32(dsm);

    const int tid = threadIdx.x;
    const int wid = tid >> 5;
    const int lane = tid & 31;
    const int m0 = blockIdx.y * 128;
    const int n0 = blockIdx.x * 128;
    const int wm = wid & 1;      // 0..1  (64 rows each)
    const int wn = wid >> 1;     // 0..3  (32 cols each)

    const __nv_bfloat16* mats[4] = {
        Ahi + (size_t)m0 * K, Alo + (size_t)m0 * K,
        Bhi + (size_t)n0 * K, Blo + (size_t)n0 * K };

    float acc[4][4][4];
#pragma unroll
    for (int a = 0; a < 4; a++)
#pragma unroll
        for (int b = 0; b < 4; b++)
#pragma unroll
            for (int c = 0; c < 4; c++) acc[a][b][c] = 0.0f;

    const int NS = K >> 5;

    // fill stage 0, slab 0
    {
#pragma unroll
        for (int i = 0; i < 8; i++) {
            int idx = tid + i * 256;
            int mat = idx >> 9, rem = idx & 511, row = rem >> 2, ch = rem & 3;
            const char* src = (const char*)(mats[mat] + (size_t)row * K + ch * 8);
            uint32_t dst = sbase + mat * 8192 + swz64((uint32_t)(row * 64 + ch * 16));
            CP16(dst, src);
        }
        CP_COMMIT();
    }

    for (int it = 0; it < NS; ++it) {
        if (it + 1 < NS) {
            const int st = (it + 1) & 1;
            const int koff = (it + 1) * 32;
#pragma unroll
            for (int i = 0; i < 8; i++) {
                int idx = tid + i * 256;
                int mat = idx >> 9, rem = idx & 511, row = rem >> 2, ch = rem & 3;
                const char* src = (const char*)(mats[mat] + (size_t)row * K + koff + ch * 8);
                uint32_t dst = sbase + st * 32768 + mat * 8192 + swz64((uint32_t)(row * 64 + ch * 16));
                CP16(dst, src);
            }
            CP_COMMIT();
        } else {
            CP_COMMIT();
        }
        CP_WAIT1();
        __syncthreads();

        const uint32_t sb = sbase + (it & 1) * 32768;

#pragma unroll
        for (int kk = 0; kk < 2; kk++) {
            uint32_t ah[4][4], al[4][4], bh[2][4], bl[2][4];
#pragma unroll
            for (int mi = 0; mi < 4; mi++) {
                int row = wm * 64 + mi * 16 + (lane & 15);
                int ch = kk * 2 + (lane >> 4);
                uint32_t off = swz64((uint32_t)(row * 64 + ch * 16));
                LDM4(ah[mi], sb + off);
                LDM4(al[mi], sb + 8192 + off);
            }
#pragma unroll
            for (int ni = 0; ni < 2; ni++) {
                int row = wn * 32 + ni * 16 + (lane & 7) + ((lane >> 4) & 1) * 8;
                int ch = kk * 2 + ((lane >> 3) & 1);
                uint32_t off = swz64((uint32_t)(row * 64 + ch * 16));
                LDM4(bh[ni], sb + 16384 + off);
                LDM4(bl[ni], sb + 24576 + off);
            }
#pragma unroll
            for (int mi = 0; mi < 4; mi++)
#pragma unroll
                for (int j = 0; j < 4; j++) {
                    const uint32_t* bhp = bh[j >> 1];
                    const uint32_t* blp = bl[j >> 1];
                    const int o = (j & 1) * 2;
                    MMA_BF16(acc[mi][j], ah[mi], bhp[o], bhp[o + 1]);
                    MMA_BF16(acc[mi][j], ah[mi], blp[o], blp[o + 1]);
                    MMA_BF16(acc[mi][j], al[mi], bhp[o], bhp[o + 1]);
                }
        }
        __syncthreads();
    }

    // epilogue
#pragma unroll
    for (int mi = 0; mi < 4; mi++)
#pragma unroll
        for (int j = 0; j < 4; j++) {
            int rr = m0 + wm * 64 + mi * 16 + (lane >> 2);
            int cc = n0 + wn * 32 + j * 8 + (lane & 3) * 2;
            *(float2*)&C[(size_t)rr * N + cc]       = make_float2(acc[mi][j][0], acc[mi][j][1]);
            *(float2*)&C[(size_t)(rr + 8) * N + cc] = make_float2(acc[mi][j][2], acc[mi][j][3]);
        }
}

// ---------------------------------------------------------------------------
// RoPE + layout + bf16 hi/lo split (reads packed QKVp).
// Q pre-scaled by 1/sqrt(HD)=0.125.
// ---------------------------------------------------------------------------
__global__ void rope_kernel(const int* __restrict__ tp, int n_pos)
{
    const int TOT = B_ * T_ * (HQ_ + 2 * HKV_) * (HD_ / 2);
    int idx = blockIdx.x * blockDim.x + threadIdx.x;
    if (idx >= TOT) return;

    int i    = idx & 31;
    int rest = idx >> 5;
    int h48  = rest % 48;
    int rest2 = rest / 48;
    int t    = rest2 & (T_ - 1);
    int b    = rest2 >> 11;

    int pos = (n_pos == B_ * T_) ? tp[b * T_ + t] : tp[t];

    // 10000^(-2i/64)
    float invf = exp2f((float)(2 * i) * (-13.287712379549449f / (float)HD_));
    float s, c;
    sincosf((float)pos * invf, &s, &c);

    const float* rowp = g_QKVp + (size_t)(b * T_ + t) * NQKV_;
    float2 o;
    size_t dsto;
    __nv_bfloat16 *hi, *lo;

    if (h48 < HQ_) {
        int h = h48;
        const float2 v = *(const float2*)&rowp[h * HD_ + 2 * i];
        o.x = (v.x * c - v.y * s) * 0.125f;
        o.y = (v.x * s + v.y * c) * 0.125f;
        dsto = ((size_t)(b * HQ_ + h) * T_ + t) * HD_ + 2 * i;
        hi = g_Qhi; lo = g_Qlo;
    } else if (h48 < HQ_ + HKV_) {
        int kv = h48 - HQ_;
        const float2 v = *(const float2*)&rowp[2048 + kv * HD_ + 2 * i];
        o.x = v.x * c - v.y * s;
        o.y = v.x * s + v.y * c;
        dsto = ((size_t)(b * HKV_ + kv) * T_ + t) * HD_ + 2 * i;
        hi = g_Khi; lo = g_Klo;
    } else {
        int kv = h48 - HQ_ - HKV_;
        const float2 v = *(const float2*)&rowp[2560 + kv * HD_ + 2 * i];
        o = v;
        dsto = ((size_t)(b * HKV_ + kv) * T_ + t) * HD_ + 2 * i;
        hi = g_Vhi; lo = g_Vlo;
    }
    __nv_bfloat16 hx = __float2bfloat16(o.x);
    __nv_bfloat16 hy = __float2bfloat16(o.y);
    __nv_bfloat16 lx = __float2bfloat16(o.x - __bfloat162float(hx));
    __nv_bfloat16 ly = __float2bfloat16(o.y - __bfloat162float(hy));
    *(__nv_bfloat162*)&hi[dsto] = __nv_bfloat162{hx, hy};
    *(__nv_bfloat162*)&lo[dsto] = __nv_bfloat162{lx, ly};
}

// ---------------------------------------------------------------------------
// Flash attention on mma.sync (bf16 hi/lo split, fp32 accum).
// Block: 128 thr (4 warps), BM=64, BN=64. 2-stage KV pipeline, 64KB smem.
// m_tile mapped DESCENDING from blockIdx.x for wave load-balance.
// Epilogue writes bf16 hi/lo splits directly (feeds WO GEMM).
// ---------------------------------------------------------------------------
__global__ __launch_bounds__(128) void attn_mma_kernel()
{
    extern __shared__ char dsm[];
    const uint32_t sbase = smem_u32(dsm);

    const int tid = threadIdx.x;
    const int wid = tid >> 5;      // 0..3
    const int lane = tid & 31;
    const int m_tile = (T_ / 64 - 1) - blockIdx.x;   // descending work order
    const int h = blockIdx.y;
    const int b = blockIdx.z;
    const int kv = h >> 2;

    const __nv_bfloat16* Qhi_g = g_Qhi + ((size_t)(b * HQ_ + h) * T_ + m_tile * 64) * HD_;
    const __nv_bfloat16* Qlo_g = g_Qlo + ((size_t)(b * HQ_ + h) * T_ + m_tile * 64) * HD_;
    const __nv_bfloat16* kvmats[4] = {
        g_Khi + (size_t)(b * HKV_ + kv) * T_ * HD_,
        g_Klo + (size_t)(b * HKV_ + kv) * T_ * HD_,
        g_Vhi + (size_t)(b * HKV_ + kv) * T_ * HD_,
        g_Vlo + (size_t)(b * HKV_ + kv) * T_ * HD_ };

    // prologue: Q into buf1 region (hi at +32768, lo at +40960)
    {
#pragma unroll
        for (int i = 0; i < 8; i++) {
            int idx = tid + i * 128;
            int mat = idx >> 9, rem = idx & 511, row = rem >> 3, ch = rem & 7;
            const char* src = (const char*)((mat ? Qlo_g : Qhi_g) + (size_t)row * 64 + ch * 8);
            uint32_t dst = sbase + 32768 + mat * 8192 + swz128((uint32_t)(row * 128 + ch * 16));
            CP16(dst, src);
        }
        CP_COMMIT();
    }
    // KV tile 0 -> stage 0
    {
#pragma unroll
        for (int i = 0; i < 16; i++) {
            int idx = tid + i * 128;
            int mat = idx >> 9, rem = idx & 511, row = rem >> 3, ch = rem & 7;
            const char* src = (const char*)(kvmats[mat] + (size_t)row * 64 + ch * 8);
            uint32_t dst = sbase + mat * 8192 + swz128((uint32_t)(row * 128 + ch * 16));
            CP16(dst, src);
        }
        CP_COMMIT();
    }
    CP_WAIT1();          // Q complete
    __syncthreads();

    // extract Q fragments (per-warp rows wid*16..+15); Q region is read-only after
    uint32_t qh[4][4], ql[4][4];
#pragma unroll
    for (int kk = 0; kk < 4; kk++) {
        int row = wid * 16 + (lane & 15);
        int ch = kk * 2 + (lane >> 4);
        uint32_t off = swz128((uint32_t)(row * 128 + ch * 16));
        LDM4(qh[kk], sbase + 32768 + off);
        LDM4(ql[kk], sbase + 32768 + 8192 + off);
    }

    float ml0 = -1e30f, ml1 = -1e30f, ll0 = 0.0f, ll1 = 0.0f;
    float oacc[8][4];
#pragma unroll
    for (int d = 0; d < 8; d++)
#pragma unroll
        for (int c = 0; c < 4; c++) oacc[d][c] = 0.0f;

    for (int nt = 0; nt <= m_tile; ++nt) {
        // prefetch next KV tile
        if (nt + 1 <= m_tile) {
            const int st = (nt + 1) & 1;
            const size_t toff = (size_t)(nt + 1) * 64 * 64;
#pragma unroll
            for (int i = 0; i < 16; i++) {
                int idx = tid + i * 128;
                int mat = idx >> 9, rem = idx & 511, row = rem >> 3, ch = rem & 7;
                const char* src = (const char*)(kvmats[mat] + toff + (size_t)row * 64 + ch * 8);
                uint32_t dst = sbase + st * 32768 + mat * 8192 + swz128((uint32_t)(row * 128 + ch * 16));
                CP16(dst, src);
            }
            CP_COMMIT();
        } else {
            CP_COMMIT();
        }
        CP_WAIT1();
        __syncthreads();

        const uint32_t sb = sbase + (nt & 1) * 32768;

        // ---- S = Q K^T ----
        float s[8][4];
#pragma unroll
        for (int j = 0; j < 8; j++)
#pragma unroll
            for (int c = 0; c < 4; c++) s[j][c] = 0.0f;

#pragma unroll
        for (int kk = 0; kk < 4; kk++) {
#pragma unroll
            for (int ni = 0; ni < 4; ni++) {
                int row = ni * 16 + (lane & 7) + ((lane >> 4) & 1) * 8;
                int ch = kk * 2 + ((lane >> 3) & 1);
                uint32_t off = swz128((uint32_t)(row * 128 + ch * 16));
                uint32_t kh[4], kl[4];
                LDM4(kh, sb + off);
                LDM4(kl, sb + 8192 + off);
                MMA_BF16(s[2 * ni],     qh[kk], kh[0], kh[1]);
                MMA_BF16(s[2 * ni],     qh[kk], kl[0], kl[1]);
                MMA_BF16(s[2 * ni],     ql[kk], kh[0], kh[1]);
                MMA_BF16(s[2 * ni + 1], qh[kk], kh[2], kh[3]);
                MMA_BF16(s[2 * ni + 1], qh[kk], kl[2], kl[3]);
                MMA_BF16(s[2 * ni + 1], ql[kk], kh[2], kh[3]);
            }
        }

        // ---- mask + online softmax ----
        const int r0g = m_tile * 64 + wid * 16 + (lane >> 2);
        const int r1g = r0g + 8;
        const int nb = nt * 64 + (lane & 3) * 2;
        if (nt == m_tile) {
#pragma unroll
            for (int j = 0; j < 8; j++) {
                int n = nb + 8 * j;
                if (n     > r0g) s[j][0] = -1e30f;
                if (n + 1 > r0g) s[j][1] = -1e30f;
                if (n     > r1g) s[j][2] = -1e30f;
                if (n + 1 > r1g) s[j][3] = -1e30f;
            }
        }
        float mx0 = -1e30f, mx1 = -1e30f;
#pragma unroll
        for (int j = 0; j < 8; j++) {
            mx0 = fmaxf(mx0, fmaxf(s[j][0], s[j][1]));
            mx1 = fmaxf(mx1, fmaxf(s[j][2], s[j][3]));
        }
        mx0 = fmaxf(mx0, __shfl_xor_sync(0xffffffffu, mx0, 1));
        mx0 = fmaxf(mx0, __shfl_xor_sync(0xffffffffu, mx0, 2));
        mx1 = fmaxf(mx1, __shfl_xor_sync(0xffffffffu, mx1, 1));
        mx1 = fmaxf(mx1, __shfl_xor_sync(0xffffffffu, mx1, 2));

        const float mn0 = fmaxf(ml0, mx0);
        const float mn1 = fmaxf(ml1, mx1);
        const float al0 = __expf(ml0 - mn0);
        const float al1 = __expf(ml1 - mn1);

        uint32_t ph[4][4], pl[4][4];
        float sum0 = 0.0f, sum1 = 0.0f;
#pragma unroll
        for (int j = 0; j < 8; j++) {
            float p0 = __expf(s[j][0] - mn0);
            float p1 = __expf(s[j][1] - mn0);
            float p2 = __expf(s[j][2] - mn1);
            float p3 = __expf(s[j][3] - mn1);
            sum0 += p0 + p1;
            sum1 += p2 + p3;
            float h0 = __bfloat162float(__float2bfloat16(p0));
            float h1 = __bfloat162float(__float2bfloat16(p1));
            float h2 = __bfloat162float(__float2bfloat16(p2));
            float h3 = __bfloat162float(__float2bfloat16(p3));
            const int kf = j >> 1;
            if ((j & 1) == 0) {
                ph[kf][0] = pack_bf16(h0, h1);
                ph[kf][1] = pack_bf16(h2, h3);
                pl[kf][0] = pack_bf16(p0 - h0, p1 - h1);
                pl[kf][1] = pack_bf16(p2 - h2, p3 - h3);
            } else {
                ph[kf][2] = pack_bf16(h0, h1);
                ph[kf][3] = pack_bf16(h2, h3);
                pl[kf][2] = pack_bf16(p0 - h0, p1 - h1);
                pl[kf][3] = pack_bf16(p2 - h2, p3 - h3);
            }
        }
        sum0 += __shfl_xor_sync(0xffffffffu, sum0, 1);
        sum0 += __shfl_xor_sync(0xffffffffu, sum0, 2);
        sum1 += __shfl_xor_sync(0xffffffffu, sum1, 1);
        sum1 += __shfl_xor_sync(0xffffffffu, sum1, 2);

        ll0 = ll0 * al0 + sum0;
        ll1 = ll1 * al1 + sum1;
        ml0 = mn0; ml1 = mn1;

        // rescale O
#pragma unroll
        for (int d = 0; d < 8; d++) {
            oacc[d][0] *= al0; oacc[d][1] *= al0;
            oacc[d][2] *= al1; oacc[d][3] *= al1;
        }

        // ---- O += P V ----
#pragma unroll
        for (int kf = 0; kf < 4; kf++) {
#pragma unroll
            for (int di = 0; di < 4; di++) {
                int row = kf * 16 + (lane & 7) + ((lane >> 3) & 1) * 8;
                int ch = di * 2 + (lane >> 4);
                uint32_t off = swz128((uint32_t)(row * 128 + ch * 16));
                uint32_t vh[4], vl[4];
                LDM4T(vh, sb + 16384 + off);
                LDM4T(vl, sb + 24576 + off);
                MMA_BF16(oacc[2 * di],     ph[kf], vh[0], vh[1]);
                MMA_BF16(oacc[2 * di],     ph[kf], vl[0], vl[1]);
                MMA_BF16(oacc[2 * di],     pl[kf], vh[0], vh[1]);
                MMA_BF16(oacc[2 * di + 1], ph[kf], vh[2], vh[3]);
                MMA_BF16(oacc[2 * di + 1], ph[kf], vl[2], vl[3]);
                MMA_BF16(oacc[2 * di + 1], pl[kf], vh[2], vh[3]);
            }
        }
        __syncthreads();
    }

    // epilogue: normalize, split to bf16 hi/lo, write (b,t,h*64+d)
    const float inv0 = 1.0f / ll0;
    const float inv1 = 1.0f / ll1;
    const int t0 = m_tile * 64 + wid * 16 + (lane >> 2);
#pragma unroll
    for (int dd = 0; dd < 8; dd++) {
        int d = dd * 8 + (lane & 3) * 2;
        size_t o0 = ((size_t)(b * T_ + t0) * DM_) + h * HD_ + d;
        size_t o1 = o0 + (size_t)8 * DM_;
        float v0 = oacc[dd][0] * inv0, v1 = oacc[dd][1] * inv0;
        float v2 = oacc[dd][2] * inv1, v3 = oacc[dd][3] * inv1;
        __nv_bfloat16 h0 = __float2bfloat16(v0), h1 = __float2bfloat16(v1);
        __nv_bfloat16 h2 = __float2bfloat16(v2), h3 = __float2bfloat16(v3);
        *(__nv_bfloat162*)&g_ohi[o0] = __nv_bfloat162{h0, h1};
        *(__nv_bfloat162*)&g_olo[o0] = __nv_bfloat162{
            __float2bfloat16(v0 - __bfloat162float(h0)),
            __float2bfloat16(v1 - __bfloat162float(h1))};
        *(__nv_bfloat162*)&g_ohi[o1] = __nv_bfloat162{h2, h3};
        *(__nv_bfloat162*)&g_olo[o1] = __nv_bfloat162{
            __float2bfloat16(v2 - __bfloat162float(h2)),
            __float2bfloat16(v3 - __bfloat162float(h3))};
    }
}

// ---------------------------------------------------------------------------
// Launch
// ---------------------------------------------------------------------------
extern "C" void kernel_launch(void* const* d_in, const int* in_sizes, int n_in,
                              void* d_out, int out_size)
{
    const float* x  = (const float*)d_in[0];
    const int*   tp = (const int*)d_in[1];
    const float* WQ = (const float*)d_in[2];
    const float* WK = (const float*)d_in[3];
    const float* WV = (const float*)d_in[4];
    const float* WO = (const float*)d_in[5];
    float* out = (float*)d_out;

    float* QKVp;
    cudaGetSymbolAddress((void**)&QKVp, g_QKVp);
    __nv_bfloat16 *xhi, *xlo, *wqkvhi, *wqkvlo, *wohi, *wolo, *ohi, *olo;
    cudaGetSymbolAddress((void**)&xhi, g_xhi);       cudaGetSymbolAddress((void**)&xlo, g_xlo);
    cudaGetSymbolAddress((void**)&wqkvhi, g_wqkvhi); cudaGetSymbolAddress((void**)&wqkvlo, g_wqkvlo);
    cudaGetSymbolAddress((void**)&wohi, g_wohi);     cudaGetSymbolAddress((void**)&wolo, g_wolo);
    cudaGetSymbolAddress((void**)&ohi, g_ohi);       cudaGetSymbolAddress((void**)&olo, g_olo);

    cudaFuncSetAttribute(gemm_mma_kernel, cudaFuncAttributeMaxDynamicSharedMemorySize, 65536);
    cudaFuncSetAttribute(attn_mma_kernel, cudaFuncAttributeMaxDynamicSharedMemorySize, 65536);

    // 1: x split
    {
        int n = MROWS_ * DM_;
        split_kernel<<<n/4/256, 256>>>(x, xhi, xlo, n);
    }
    // 2: merged WQ/WK/WV split
    {
        int n = NQKV_ * DM_;
        split_wqkv_kernel<<<n/4/256, 256>>>(WQ, WK, WV, wqkvhi, wqkvlo);
    }
    // 3: WO split
    {
        int n = DM_ * DM_;
        split_kernel<<<n/4/256, 256>>>(WO, wohi, wolo, n);
    }
    // 4: fused QKV projection
    {
        dim3 g(NQKV_ / 128, MROWS_ / 128);
        gemm_mma_kernel<<<g, 256, 65536>>>(xhi, xlo, wqkvhi, wqkvlo, QKVp, MROWS_, NQKV_, DM_);
    }
    // 5: RoPE + layout + bf16 split
    {
        const int TOT = B_ * T_ * (HQ_ + 2 * HKV_) * (HD_ / 2);
        rope_kernel<<<(TOT + 255) / 256, 256>>>(tp, in_sizes[1]);
    }
    // 6: flash attention (writes ohi/olo directly)
    {
        dim3 ga(T_ / 64, HQ_, B_);
        attn_mma_kernel<<<ga, 128, 65536>>>();
    }
    // 7: output projection
    {
        dim3 go(DM_ / 128, MROWS_ / 128);
        gemm_mma_kernel<<<go, 256, 65536>>>(ohi, olo, wohi, wolo, out, MROWS_, DM_, DM_);
    }
}

// round 14
// speedup vs baseline: 1.1539x; 1.1539x over previous
#include <cuda_runtime.h>
#include <cuda_bf16.h>
#include <math.h>
#include <stdint.h>

// Problem constants
#define B_   2
#define T_   2048
#define DM_  2048
#define HQ_  32
#define HKV_ 8
#define HD_  64
#define G_   4
#define MROWS_ (B_*T_)   // 4096
#define NQKV_ 3072       // 2048 Q + 512 K + 512 V

// ---------------------------------------------------------------------------
// Scratch (device globals)
// ---------------------------------------------------------------------------
__device__ float g_QKVp[(size_t)MROWS_ * NQKV_];       // x @ [WQ;WK;WV]^T fp32

__device__ __nv_bfloat16 g_xhi[(size_t)MROWS_ * DM_];
__device__ __nv_bfloat16 g_xlo[(size_t)MROWS_ * DM_];
__device__ __nv_bfloat16 g_wqkvhi[(size_t)NQKV_ * DM_];
__device__ __nv_bfloat16 g_wqkvlo[(size_t)NQKV_ * DM_];
__device__ __nv_bfloat16 g_wohi[(size_t)DM_ * DM_];
__device__ __nv_bfloat16 g_wolo[(size_t)DM_ * DM_];
__device__ __nv_bfloat16 g_ohi[(size_t)MROWS_ * DM_];
__device__ __nv_bfloat16 g_olo[(size_t)MROWS_ * DM_];

// bf16 hi/lo attention operands, (b,h,t,d) layout
__device__ __nv_bfloat16 g_Qhi[(size_t)B_ * HQ_ * T_ * HD_];
__device__ __nv_bfloat16 g_Qlo[(size_t)B_ * HQ_ * T_ * HD_];
__device__ __nv_bfloat16 g_Khi[(size_t)B_ * HKV_ * T_ * HD_];
__device__ __nv_bfloat16 g_Klo[(size_t)B_ * HKV_ * T_ * HD_];
__device__ __nv_bfloat16 g_Vhi[(size_t)B_ * HKV_ * T_ * HD_];
__device__ __nv_bfloat16 g_Vlo[(size_t)B_ * HKV_ * T_ * HD_];

// ---------------------------------------------------------------------------
// Helpers
// ---------------------------------------------------------------------------
__device__ __forceinline__ uint32_t smem_u32(const void* p) {
    uint32_t a;
    asm("{ .reg .u64 t; cvta.to.shared.u64 t, %1; cvt.u32.u64 %0, t; }" : "=r"(a) : "l"(p));
    return a;
}
__device__ __forceinline__ uint32_t swz128(uint32_t off) { return off ^ ((off >> 3) & 0x70); }
__device__ __forceinline__ uint32_t swz64 (uint32_t off) { return off ^ ((off >> 3) & 0x30); }

__device__ __forceinline__ uint32_t pack_bf16(float lo, float hi) {
    __nv_bfloat162 t = __floats2bfloat162_rn(lo, hi);
    return *(uint32_t*)&t;
}

#define CP16(dst, src) \
    asm volatile("cp.async.cg.shared.global [%0], [%1], 16;" :: "r"(dst), "l"(src))
#define CP_COMMIT() asm volatile("cp.async.commit_group;" ::: "memory")
#define CP_WAIT1()  asm volatile("cp.async.wait_group 1;" ::: "memory")

#define LDM4(R, addr) \
    asm volatile("ldmatrix.sync.aligned.m8n8.x4.shared.b16 {%0,%1,%2,%3}, [%4];" \
        : "=r"((R)[0]), "=r"((R)[1]), "=r"((R)[2]), "=r"((R)[3]) : "r"(addr))
#define LDM4T(R, addr) \
    asm volatile("ldmatrix.sync.aligned.m8n8.x4.trans.shared.b16 {%0,%1,%2,%3}, [%4];" \
        : "=r"((R)[0]), "=r"((R)[1]), "=r"((R)[2]), "=r"((R)[3]) : "r"(addr))

#define MMA_BF16(C, A, b0, b1) \
    asm volatile("mma.sync.aligned.m16n8k16.row.col.f32.bf16.bf16.f32 " \
        "{%0,%1,%2,%3}, {%4,%5,%6,%7}, {%8,%9}, {%0,%1,%2,%3};" \
        : "+f"((C)[0]), "+f"((C)[1]), "+f"((C)[2]), "+f"((C)[3]) \
        : "r"((A)[0]), "r"((A)[1]), "r"((A)[2]), "r"((A)[3]), "r"(b0), "r"(b1))

// ---------------------------------------------------------------------------
// fp32 -> bf16 hi/lo split (single input)
// ---------------------------------------------------------------------------
__global__ __launch_bounds__(256) void split_kernel(
    const float* __restrict__ in, __nv_bfloat16* __restrict__ hi,
    __nv_bfloat16* __restrict__ lo, int n)
{
    int i = (blockIdx.x * 256 + threadIdx.x) * 4;
    if (i >= n) return;
    float4 v = *(const float4*)(in + i);
    __nv_bfloat16 h0 = __float2bfloat16(v.x);
    __nv_bfloat16 h1 = __float2bfloat16(v.y);
    __nv_bfloat16 h2 = __float2bfloat16(v.z);
    __nv_bfloat16 h3 = __float2bfloat16(v.w);
    __nv_bfloat16 l0 = __float2bfloat16(v.x - __bfloat162float(h0));
    __nv_bfloat16 l1 = __float2bfloat16(v.y - __bfloat162float(h1));
    __nv_bfloat16 l2 = __float2bfloat16(v.z - __bfloat162float(h2));
    __nv_bfloat16 l3 = __float2bfloat16(v.w - __bfloat162float(h3));
    __nv_bfloat162* hp = (__nv_bfloat162*)(hi + i);
    __nv_bfloat162* lp = (__nv_bfloat162*)(lo + i);
    hp[0] = __nv_bfloat162{h0, h1}; hp[1] = __nv_bfloat162{h2, h3};
    lp[0] = __nv_bfloat162{l0, l1}; lp[1] = __nv_bfloat162{l2, l3};
}

// ---------------------------------------------------------------------------
// Merged WQ/WK/WV split into packed [3072,2048] hi/lo buffers (one launch)
// ---------------------------------------------------------------------------
__global__ __launch_bounds__(256) void split_wqkv_kernel(
    const float* __restrict__ WQ, const float* __restrict__ WK,
    const float* __restrict__ WV,
    __nv_bfloat16* __restrict__ hi, __nv_bfloat16* __restrict__ lo)
{
    const int NQ = 2048 * DM_;
    const int NK = 512 * DM_;
    int i = (blockIdx.x * 256 + threadIdx.x) * 4;
    if (i >= NQKV_ * DM_) return;
    const float* src;
    int off;
    if (i < NQ)            { src = WQ; off = i; }
    else if (i < NQ + NK)  { src = WK; off = i - NQ; }
    else                   { src = WV; off = i - NQ - NK; }
    float4 v = *(const float4*)(src + off);
    __nv_bfloat16 h0 = __float2bfloat16(v.x);
    __nv_bfloat16 h1 = __float2bfloat16(v.y);
    __nv_bfloat16 h2 = __float2bfloat16(v.z);
    __nv_bfloat16 h3 = __float2bfloat16(v.w);
    __nv_bfloat16 l0 = __float2bfloat16(v.x - __bfloat162float(h0));
    __nv_bfloat16 l1 = __float2bfloat16(v.y - __bfloat162float(h1));
    __nv_bfloat16 l2 = __float2bfloat16(v.z - __bfloat162float(h2));
    __nv_bfloat16 l3 = __float2bfloat16(v.w - __bfloat162float(h3));
    __nv_bfloat162* hp = (__nv_bfloat162*)(hi + i);
    __nv_bfloat162* lp = (__nv_bfloat162*)(lo + i);
    hp[0] = __nv_bfloat162{h0, h1}; hp[1] = __nv_bfloat162{h2, h3};
    lp[0] = __nv_bfloat162{l0, l1}; lp[1] = __nv_bfloat162{l2, l3};
}

// ---------------------------------------------------------------------------
// mma.sync split-bf16 GEMM: C[M,N] = A[M,K] @ B[N,K]^T (fp32-quality)
// CTA 128x128, 8 warps (2x4), warp tile 64x32, K-slab 32, cp.async 2-stage.
// Fragment liveness reduced (A loaded per-mi) + launch_bounds(256,2) so
// TWO CTAs fit per SM (reg cap 128).
// ---------------------------------------------------------------------------
__global__ __launch_bounds__(256, 2) void gemm_mma_kernel(
    const __nv_bfloat16* __restrict__ Ahi, const __nv_bfloat16* __restrict__ Alo,
    const __nv_bfloat16* __restrict__ Bhi, const __nv_bfloat16* __restrict__ Blo,
    float* __restrict__ C, int M, int N, int K)
{
    extern __shared__ char dsm[];
    const uint32_t sbase = smem_u32(dsm);

    const int tid = threadIdx.x;
    const int wid = tid >> 5;
    const int lane = tid & 31;
    const int m0 = blockIdx.y * 128;
    const int n0 = blockIdx.x * 128;
    const int wm = wid & 1;      // 0..1  (64 rows each)
    const int wn = wid >> 1;     // 0..3  (32 cols each)

    const __nv_bfloat16* mats[4] = {
        Ahi + (size_t)m0 * K, Alo + (size_t)m0 * K,
        Bhi + (size_t)n0 * K, Blo + (size_t)n0 * K };

    float acc[4][4][4];
#pragma unroll
    for (int a = 0; a < 4; a++)
#pragma unroll
        for (int b = 0; b < 4; b++)
#pragma unroll
            for (int c = 0; c < 4; c++) acc[a][b][c] = 0.0f;

    const int NS = K >> 5;

    // fill stage 0, slab 0
    {
#pragma unroll
        for (int i = 0; i < 8; i++) {
            int idx = tid + i * 256;
            int mat = idx >> 9, rem = idx & 511, row = rem >> 2, ch = rem & 3;
            const char* src = (const char*)(mats[mat] + (size_t)row * K + ch * 8);
            uint32_t dst = sbase + mat * 8192 + swz64((uint32_t)(row * 64 + ch * 16));
            CP16(dst, src);
        }
        CP_COMMIT();
    }

    for (int it = 0; it < NS; ++it) {
        if (it + 1 < NS) {
            const int st = (it + 1) & 1;
            const int koff = (it + 1) * 32;
#pragma unroll
            for (int i = 0; i < 8; i++) {
                int idx = tid + i * 256;
                int mat = idx >> 9, rem = idx & 511, row = rem >> 2, ch = rem & 3;
                const char* src = (const char*)(mats[mat] + (size_t)row * K + koff + ch * 8);
                uint32_t dst = sbase + st * 32768 + mat * 8192 + swz64((uint32_t)(row * 64 + ch * 16));
                CP16(dst, src);
            }
            CP_COMMIT();
        } else {
            CP_COMMIT();
        }
        CP_WAIT1();
        __syncthreads();

        const uint32_t sb = sbase + (it & 1) * 32768;

#pragma unroll
        for (int kk = 0; kk < 2; kk++) {
            // B fragments first (shared across all mi)
            uint32_t bh[2][4], bl[2][4];
#pragma unroll
            for (int ni = 0; ni < 2; ni++) {
                int row = wn * 32 + ni * 16 + (lane & 7) + ((lane >> 4) & 1) * 8;
                int ch = kk * 2 + ((lane >> 3) & 1);
                uint32_t off = swz64((uint32_t)(row * 64 + ch * 16));
                LDM4(bh[ni], sb + 16384 + off);
                LDM4(bl[ni], sb + 24576 + off);
            }
            // A fragments per-mi (reduced liveness: 8 regs instead of 32)
#pragma unroll
            for (int mi = 0; mi < 4; mi++) {
                uint32_t ah[4], al[4];
                int row = wm * 64 + mi * 16 + (lane & 15);
                int ch = kk * 2 + (lane >> 4);
                uint32_t off = swz64((uint32_t)(row * 64 + ch * 16));
                LDM4(ah, sb + off);
                LDM4(al, sb + 8192 + off);
#pragma unroll
                for (int j = 0; j < 4; j++) {
                    const uint32_t* bhp = bh[j >> 1];
                    const uint32_t* blp = bl[j >> 1];
                    const int o = (j & 1) * 2;
                    MMA_BF16(acc[mi][j], ah, bhp[o], bhp[o + 1]);
                    MMA_BF16(acc[mi][j], ah, blp[o], blp[o + 1]);
                    MMA_BF16(acc[mi][j], al, bhp[o], bhp[o + 1]);
                }
            }
        }
        __syncthreads();
    }

    // epilogue
#pragma unroll
    for (int mi = 0; mi < 4; mi++)
#pragma unroll
        for (int j = 0; j < 4; j++) {
            int rr = m0 + wm * 64 + mi * 16 + (lane >> 2);
            int cc = n0 + wn * 32 + j * 8 + (lane & 3) * 2;
            *(float2*)&C[(size_t)rr * N + cc]       = make_float2(acc[mi][j][0], acc[mi][j][1]);
            *(float2*)&C[(size_t)(rr + 8) * N + cc] = make_float2(acc[mi][j][2], acc[mi][j][3]);
        }
}

// ---------------------------------------------------------------------------
// RoPE + layout + bf16 hi/lo split (reads packed QKVp).
// Q pre-scaled by 1/sqrt(HD)=0.125.
// ---------------------------------------------------------------------------
__global__ void rope_kernel(const int* __restrict__ tp, int n_pos)
{
    const int TOT = B_ * T_ * (HQ_ + 2 * HKV_) * (HD_ / 2);
    int idx = blockIdx.x * blockDim.x + threadIdx.x;
    if (idx >= TOT) return;

    int i    = idx & 31;
    int rest = idx >> 5;
    int h48  = rest % 48;
    int rest2 = rest / 48;
    int t    = rest2 & (T_ - 1);
    int b    = rest2 >> 11;

    int pos = (n_pos == B_ * T_) ? tp[b * T_ + t] : tp[t];

    float invf = exp2f((float)(2 * i) * (-13.287712379549449f / (float)HD_));
    float s, c;
    sincosf((float)pos * invf, &s, &c);

    const float* rowp = g_QKVp + (size_t)(b * T_ + t) * NQKV_;
    float2 o;
    size_t dsto;
    __nv_bfloat16 *hi, *lo;

    if (h48 < HQ_) {
        int h = h48;
        const float2 v = *(const float2*)&rowp[h * HD_ + 2 * i];
        o.x = (v.x * c - v.y * s) * 0.125f;
        o.y = (v.x * s + v.y * c) * 0.125f;
        dsto = ((size_t)(b * HQ_ + h) * T_ + t) * HD_ + 2 * i;
        hi = g_Qhi; lo = g_Qlo;
    } else if (h48 < HQ_ + HKV_) {
        int kv = h48 - HQ_;
        const float2 v = *(const float2*)&rowp[2048 + kv * HD_ + 2 * i];
        o.x = v.x * c - v.y * s;
        o.y = v.x * s + v.y * c;
        dsto = ((size_t)(b * HKV_ + kv) * T_ + t) * HD_ + 2 * i;
        hi = g_Khi; lo = g_Klo;
    } else {
        int kv = h48 - HQ_ - HKV_;
        const float2 v = *(const float2*)&rowp[2560 + kv * HD_ + 2 * i];
        o = v;
        dsto = ((size_t)(b * HKV_ + kv) * T_ + t) * HD_ + 2 * i;
        hi = g_Vhi; lo = g_Vlo;
    }
    __nv_bfloat16 hx = __float2bfloat16(o.x);
    __nv_bfloat16 hy = __float2bfloat16(o.y);
    __nv_bfloat16 lx = __float2bfloat16(o.x - __bfloat162float(hx));
    __nv_bfloat16 ly = __float2bfloat16(o.y - __bfloat162float(hy));
    *(__nv_bfloat162*)&hi[dsto] = __nv_bfloat162{hx, hy};
    *(__nv_bfloat162*)&lo[dsto] = __nv_bfloat162{lx, ly};
}

// ---------------------------------------------------------------------------
// Flash attention on mma.sync (bf16 hi/lo split, fp32 accum).
// Block: 128 thr (4 warps), BM=64, BN=64. 2-stage KV pipeline, 64KB smem.
// (R6-proven config, ascending m_tile)
// ---------------------------------------------------------------------------
__global__ __launch_bounds__(128) void attn_mma_kernel()
{
    extern __shared__ char dsm[];
    const uint32_t sbase = smem_u32(dsm);

    const int tid = threadIdx.x;
    const int wid = tid >> 5;      // 0..3
    const int lane = tid & 31;
    const int m_tile = blockIdx.x;
    const int h = blockIdx.y;
    const int b = blockIdx.z;
    const int kv = h >> 2;

    const __nv_bfloat16* Qhi_g = g_Qhi + ((size_t)(b * HQ_ + h) * T_ + m_tile * 64) * HD_;
    const __nv_bfloat16* Qlo_g = g_Qlo + ((size_t)(b * HQ_ + h) * T_ + m_tile * 64) * HD_;
    const __nv_bfloat16* kvmats[4] = {
        g_Khi + (size_t)(b * HKV_ + kv) * T_ * HD_,
        g_Klo + (size_t)(b * HKV_ + kv) * T_ * HD_,
        g_Vhi + (size_t)(b * HKV_ + kv) * T_ * HD_,
        g_Vlo + (size_t)(b * HKV_ + kv) * T_ * HD_ };

    // prologue: Q into buf1 region (hi at +32768, lo at +40960)
    {
#pragma unroll
        for (int i = 0; i < 8; i++) {
            int idx = tid + i * 128;
            int mat = idx >> 9, rem = idx & 511, row = rem >> 3, ch = rem & 7;
            const char* src = (const char*)((mat ? Qlo_g : Qhi_g) + (size_t)row * 64 + ch * 8);
            uint32_t dst = sbase + 32768 + mat * 8192 + swz128((uint32_t)(row * 128 + ch * 16));
            CP16(dst, src);
        }
        CP_COMMIT();
    }
    // KV tile 0 -> stage 0
    {
#pragma unroll
        for (int i = 0; i < 16; i++) {
            int idx = tid + i * 128;
            int mat = idx >> 9, rem = idx & 511, row = rem >> 3, ch = rem & 7;
            const char* src = (const char*)(kvmats[mat] + (size_t)row * 64 + ch * 8);
            uint32_t dst = sbase + mat * 8192 + swz128((uint32_t)(row * 128 + ch * 16));
            CP16(dst, src);
        }
        CP_COMMIT();
    }
    CP_WAIT1();          // Q complete
    __syncthreads();

    // extract Q fragments (per-warp rows wid*16..+15)
    uint32_t qh[4][4], ql[4][4];
#pragma unroll
    for (int kk = 0; kk < 4; kk++) {
        int row = wid * 16 + (lane & 15);
        int ch = kk * 2 + (lane >> 4);
        uint32_t off = swz128((uint32_t)(row * 128 + ch * 16));
        LDM4(qh[kk], sbase + 32768 + off);
        LDM4(ql[kk], sbase + 32768 + 8192 + off);
    }
    __syncthreads();

    float ml0 = -1e30f, ml1 = -1e30f, ll0 = 0.0f, ll1 = 0.0f;
    float oacc[8][4];
#pragma unroll
    for (int d = 0; d < 8; d++)
#pragma unroll
        for (int c = 0; c < 4; c++) oacc[d][c] = 0.0f;

    for (int nt = 0; nt <= m_tile; ++nt) {
        // prefetch next KV tile
        if (nt + 1 <= m_tile) {
            const int st = (nt + 1) & 1;
            const size_t toff = (size_t)(nt + 1) * 64 * 64;
#pragma unroll
            for (int i = 0; i < 16; i++) {
                int idx = tid + i * 128;
                int mat = idx >> 9, rem = idx & 511, row = rem >> 3, ch = rem & 7;
                const char* src = (const char*)(kvmats[mat] + toff + (size_t)row * 64 + ch * 8);
                uint32_t dst = sbase + st * 32768 + mat * 8192 + swz128((uint32_t)(row * 128 + ch * 16));
                CP16(dst, src);
            }
            CP_COMMIT();
        } else {
            CP_COMMIT();
        }
        CP_WAIT1();
        __syncthreads();

        const uint32_t sb = sbase + (nt & 1) * 32768;

        // ---- S = Q K^T ----
        float s[8][4];
#pragma unroll
        for (int j = 0; j < 8; j++)
#pragma unroll
            for (int c = 0; c < 4; c++) s[j][c] = 0.0f;

#pragma unroll
        for (int kk = 0; kk < 4; kk++) {
#pragma unroll
            for (int ni = 0; ni < 4; ni++) {
                int row = ni * 16 + (lane & 7) + ((lane >> 4) & 1) * 8;
                int ch = kk * 2 + ((lane >> 3) & 1);
                uint32_t off = swz128((uint32_t)(row * 128 + ch * 16));
                uint32_t kh[4], kl[4];
                LDM4(kh, sb + off);
                LDM4(kl, sb + 8192 + off);
                MMA_BF16(s[2 * ni],     qh[kk], kh[0], kh[1]);
                MMA_BF16(s[2 * ni],     qh[kk], kl[0], kl[1]);
                MMA_BF16(s[2 * ni],     ql[kk], kh[0], kh[1]);
                MMA_BF16(s[2 * ni + 1], qh[kk], kh[2], kh[3]);
                MMA_BF16(s[2 * ni + 1], qh[kk], kl[2], kl[3]);
                MMA_BF16(s[2 * ni + 1], ql[kk], kh[2], kh[3]);
            }
        }

        // ---- mask + online softmax ----
        const int r0g = m_tile * 64 + wid * 16 + (lane >> 2);
        const int r1g = r0g + 8;
        const int nb = nt * 64 + (lane & 3) * 2;
        if (nt == m_tile) {
#pragma unroll
            for (int j = 0; j < 8; j++) {
                int n = nb + 8 * j;
                if (n     > r0g) s[j][0] = -1e30f;
                if (n + 1 > r0g) s[j][1] = -1e30f;
                if (n     > r1g) s[j][2] = -1e30f;
                if (n + 1 > r1g) s[j][3] = -1e30f;
            }
        }
        float mx0 = -1e30f, mx1 = -1e30f;
#pragma unroll
        for (int j = 0; j < 8; j++) {
            mx0 = fmaxf(mx0, fmaxf(s[j][0], s[j][1]));
            mx1 = fmaxf(mx1, fmaxf(s[j][2], s[j][3]));
        }
        mx0 = fmaxf(mx0, __shfl_xor_sync(0xffffffffu, mx0, 1));
        mx0 = fmaxf(mx0, __shfl_xor_sync(0xffffffffu, mx0, 2));
        mx1 = fmaxf(mx1, __shfl_xor_sync(0xffffffffu, mx1, 1));
        mx1 = fmaxf(mx1, __shfl_xor_sync(0xffffffffu, mx1, 2));

        const float mn0 = fmaxf(ml0, mx0);
        const float mn1 = fmaxf(ml1, mx1);
        const float al0 = __expf(ml0 - mn0);
        const float al1 = __expf(ml1 - mn1);

        uint32_t ph[4][4], pl[4][4];
        float sum0 = 0.0f, sum1 = 0.0f;
#pragma unroll
        for (int j = 0; j < 8; j++) {
            float p0 = __expf(s[j][0] - mn0);
            float p1 = __expf(s[j][1] - mn0);
            float p2 = __expf(s[j][2] - mn1);
            float p3 = __expf(s[j][3] - mn1);
            sum0 += p0 + p1;
            sum1 += p2 + p3;
            float h0 = __bfloat162float(__float2bfloat16(p0));
            float h1 = __bfloat162float(__float2bfloat16(p1));
            float h2 = __bfloat162float(__float2bfloat16(p2));
            float h3 = __bfloat162float(__float2bfloat16(p3));
            const int kf = j >> 1;
            if ((j & 1) == 0) {
                ph[kf][0] = pack_bf16(h0, h1);
                ph[kf][1] = pack_bf16(h2, h3);
                pl[kf][0] = pack_bf16(p0 - h0, p1 - h1);
                pl[kf][1] = pack_bf16(p2 - h2, p3 - h3);
            } else {
                ph[kf][2] = pack_bf16(h0, h1);
                ph[kf][3] = pack_bf16(h2, h3);
                pl[kf][2] = pack_bf16(p0 - h0, p1 - h1);
                pl[kf][3] = pack_bf16(p2 - h2, p3 - h3);
            }
        }
        sum0 += __shfl_xor_sync(0xffffffffu, sum0, 1);
        sum0 += __shfl_xor_sync(0xffffffffu, sum0, 2);
        sum1 += __shfl_xor_sync(0xffffffffu, sum1, 1);
        sum1 += __shfl_xor_sync(0xffffffffu, sum1, 2);

        ll0 = ll0 * al0 + sum0;
        ll1 = ll1 * al1 + sum1;
        ml0 = mn0; ml1 = mn1;

        // rescale O
#pragma unroll
        for (int d = 0; d < 8; d++) {
            oacc[d][0] *= al0; oacc[d][1] *= al0;
            oacc[d][2] *= al1; oacc[d][3] *= al1;
        }

        // ---- O += P V ----
#pragma unroll
        for (int kf = 0; kf < 4; kf++) {
#pragma unroll
            for (int di = 0; di < 4; di++) {
                int row = kf * 16 + (lane & 7) + ((lane >> 3) & 1) * 8;
                int ch = di * 2 + (lane >> 4);
                uint32_t off = swz128((uint32_t)(row * 128 + ch * 16));
                uint32_t vh[4], vl[4];
                LDM4T(vh, sb + 16384 + off);
                LDM4T(vl, sb + 24576 + off);
                MMA_BF16(oacc[2 * di],     ph[kf], vh[0], vh[1]);
                MMA_BF16(oacc[2 * di],     ph[kf], vl[0], vl[1]);
                MMA_BF16(oacc[2 * di],     pl[kf], vh[0], vh[1]);
                MMA_BF16(oacc[2 * di + 1], ph[kf], vh[2], vh[3]);
                MMA_BF16(oacc[2 * di + 1], ph[kf], vl[2], vl[3]);
                MMA_BF16(oacc[2 * di + 1], pl[kf], vh[2], vh[3]);
            }
        }
        __syncthreads();
    }

    // epilogue: normalize, split to bf16 hi/lo, write (b,t,h*64+d)
    const float inv0 = 1.0f / ll0;
    const float inv1 = 1.0f / ll1;
    const int t0 = m_tile * 64 + wid * 16 + (lane >> 2);
#pragma unroll
    for (int dd = 0; dd < 8; dd++) {
        int d = dd * 8 + (lane & 3) * 2;
        size_t o0 = ((size_t)(b * T_ + t0) * DM_) + h * HD_ + d;
        size_t o1 = o0 + (size_t)8 * DM_;
        float v0 = oacc[dd][0] * inv0, v1 = oacc[dd][1] * inv0;
        float v2 = oacc[dd][2] * inv1, v3 = oacc[dd][3] * inv1;
        __nv_bfloat16 h0 = __float2bfloat16(v0), h1 = __float2bfloat16(v1);
        __nv_bfloat16 h2 = __float2bfloat16(v2), h3 = __float2bfloat16(v3);
        *(__nv_bfloat162*)&g_ohi[o0] = __nv_bfloat162{h0, h1};
        *(__nv_bfloat162*)&g_olo[o0] = __nv_bfloat162{
            __float2bfloat16(v0 - __bfloat162float(h0)),
            __float2bfloat16(v1 - __bfloat162float(h1))};
        *(__nv_bfloat162*)&g_ohi[o1] = __nv_bfloat162{h2, h3};
        *(__nv_bfloat162*)&g_olo[o1] = __nv_bfloat162{
            __float2bfloat16(v2 - __bfloat162float(h2)),
            __float2bfloat16(v3 - __bfloat162float(h3))};
    }
}

// ---------------------------------------------------------------------------
// Launch
// ---------------------------------------------------------------------------
extern "C" void kernel_launch(void* const* d_in, const int* in_sizes, int n_in,
                              void* d_out, int out_size)
{
    const float* x  = (const float*)d_in[0];
    const int*   tp = (const int*)d_in[1];
    const float* WQ = (const float*)d_in[2];
    const float* WK = (const float*)d_in[3];
    const float* WV = (const float*)d_in[4];
    const float* WO = (const float*)d_in[5];
    float* out = (float*)d_out;

    float* QKVp;
    cudaGetSymbolAddress((void**)&QKVp, g_QKVp);
    __nv_bfloat16 *xhi, *xlo, *wqkvhi, *wqkvlo, *wohi, *wolo, *ohi, *olo;
    cudaGetSymbolAddress((void**)&xhi, g_xhi);       cudaGetSymbolAddress((void**)&xlo, g_xlo);
    cudaGetSymbolAddress((void**)&wqkvhi, g_wqkvhi); cudaGetSymbolAddress((void**)&wqkvlo, g_wqkvlo);
    cudaGetSymbolAddress((void**)&wohi, g_wohi);     cudaGetSymbolAddress((void**)&wolo, g_wolo);
    cudaGetSymbolAddress((void**)&ohi, g_ohi);       cudaGetSymbolAddress((void**)&olo, g_olo);

    cudaFuncSetAttribute(gemm_mma_kernel, cudaFuncAttributeMaxDynamicSharedMemorySize, 65536);
    cudaFuncSetAttribute(attn_mma_kernel, cudaFuncAttributeMaxDynamicSharedMemorySize, 65536);

    // 1: x split
    {
        int n = MROWS_ * DM_;
        split_kernel<<<n/4/256, 256>>>(x, xhi, xlo, n);
    }
    // 2: merged WQ/WK/WV split
    {
        int n = NQKV_ * DM_;
        split_wqkv_kernel<<<n/4/256, 256>>>(WQ, WK, WV, wqkvhi, wqkvlo);
    }
    // 3: WO split
    {
        int n = DM_ * DM_;
        split_kernel<<<n/4/256, 256>>>(WO, wohi, wolo, n);
    }
    // 4: fused QKV projection
    {
        dim3 g(NQKV_ / 128, MROWS_ / 128);
        gemm_mma_kernel<<<g, 256, 65536>>>(xhi, xlo, wqkvhi, wqkvlo, QKVp, MROWS_, NQKV_, DM_);
    }
    // 5: RoPE + layout + bf16 split
    {
        const int TOT = B_ * T_ * (HQ_ + 2 * HKV_) * (HD_ / 2);
        rope_kernel<<<(TOT + 255) / 256, 256>>>(tp, in_sizes[1]);
    }
    // 6: flash attention (writes ohi/olo directly)
    {
        dim3 ga(T_ / 64, HQ_, B_);
        attn_mma_kernel<<<ga, 128, 65536>>>();
    }
    // 7: output projection
    {
        dim3 go(DM_ / 128, MROWS_ / 128);
        gemm_mma_kernel<<<go, 256, 65536>>>(ohi, olo, wohi, wolo, out, MROWS_, DM_, DM_);
    }
}